// round 16
// baseline (speedup 1.0000x reference)
#include <cuda_runtime.h>
#include <cuda_bf16.h>
#include <math.h>
#include <stdint.h>

// Problem constants (fixed by the reference)
#define BB 4
#define TT 256
#define SS 16384
#define EE 256
#define HH 8
#define DD 32

#define SPLITS 16
#define SCHUNK (SS / SPLITS)          // 1024 keys per block
#define NCHUNK (SCHUNK / 64)          // 16 chunks of 64 keys
#define NTQ (TT / 64)                 // 4 query tiles
#define NPID (BB * NTQ * HH * SPLITS) // 2048 partials

// Scratch (allocation-free rule: __device__ globals)
__device__ float    g_qp[BB * TT * EE];        // projected Q (scaled by qscale*log2e)
__device__ uint32_t g_kb[BB * SS * 256];       // K proj bf16: row s, head h:
                                               //   words h*32+0..15 = hi pairs, +16..31 = lo
__device__ uint32_t g_vb[BB * SS * 256];       // V proj bf16, same layout
__device__ float    g_att[BB * TT * EE];
__device__ float    g_po[NPID * 64 * 32];
__device__ float    g_pl[NPID * 64];

// ===========================================================================
// mma.sync bf16 (sm_80+ baseline; lowers to HMMA on sm_100)
// ===========================================================================
static __device__ __forceinline__ void mma_bf16(float* d, const uint32_t* a,
                                                const uint32_t* b) {
    asm volatile(
        "mma.sync.aligned.m16n8k16.row.col.f32.bf16.bf16.f32 "
        "{%0,%1,%2,%3}, {%4,%5,%6,%7}, {%8,%9}, {%0,%1,%2,%3};"
        : "+f"(d[0]), "+f"(d[1]), "+f"(d[2]), "+f"(d[3])
        : "r"(a[0]), "r"(a[1]), "r"(a[2]), "r"(a[3]), "r"(b[0]), "r"(b[1]));
}

// One-instruction pack: word = {lo half <- x, hi half <- y}
static __device__ __forceinline__ uint32_t cvt2(float x, float y) {
    uint32_t r;
    asm("cvt.rn.bf16x2.f32 %0, %1, %2;" : "=r"(r) : "f"(y), "f"(x));
    return r;
}
// Pack hi word of (x,y) and return bf16-rounding residuals
static __device__ __forceinline__ uint32_t split2(float x, float y,
                                                  float& rx, float& ry) {
    const uint32_t h = cvt2(x, y);
    rx = x - __uint_as_float(h << 16);
    ry = y - __uint_as_float(h & 0xFFFF0000u);
    return h;
}
static __device__ __forceinline__ float ex2(float x) {
    float r;
    asm("ex2.approx.f32 %0, %1;" : "=f"(r) : "f"(x));
    return r;
}

#define GS 36   // smem row stride in words: 16 hi + 16 lo + 4 pad

// ---------------------------------------------------------------------------
// bf16-split tensor-core GEMM for K/V projections (unchanged, passing).
// ---------------------------------------------------------------------------
__global__ __launch_bounds__(256, 2)
void gemm_mma_kernel(const float* __restrict__ Xk, const float* __restrict__ Wk,
                     const float* __restrict__ bk,
                     const float* __restrict__ Xv, const float* __restrict__ Wv,
                     const float* __restrict__ bv)
{
    __shared__ uint32_t sX[128 * GS];
    __shared__ uint32_t sW[128 * GS];

    const int tid  = threadIdx.x;
    const int wid  = tid >> 5;
    const int lane = tid & 31;
    const int r4 = lane >> 2;
    const int p  = lane & 3;
    const int n0 = blockIdx.x * 128;
    const int m0 = blockIdx.y * 128;
    const float* X    = blockIdx.z ? Xv : Xk;
    const float* W    = blockIdx.z ? Wv : Wk;
    const float* bias = blockIdx.z ? bv : bk;
    uint32_t*    OB   = blockIdx.z ? g_vb : g_kb;

    const int mw = (wid & 3) * 32;
    const int nw = (wid >> 2) * 64;

    float d[2][8][4];
#pragma unroll
    for (int i = 0; i < 2; i++)
#pragma unroll
        for (int j = 0; j < 8; j++)
#pragma unroll
            for (int q = 0; q < 4; q++) d[i][j][q] = 0.f;

    for (int ch = 0; ch < 8; ch++) {
        const int kc0 = ch * 32;
        float4 xf[4], wf[4];
#pragma unroll
        for (int u = 0; u < 4; u++) {
            const int idx = tid + u * 256;
            const int r   = idx >> 3;
            const int cq  = (idx & 7) * 4;
            xf[u] = *(const float4*)(X + (size_t)(m0 + r) * EE + kc0 + cq);
            wf[u] = *(const float4*)(W + (size_t)(n0 + r) * EE + kc0 + cq);
        }
        __syncthreads();
#pragma unroll
        for (int u = 0; u < 4; u++) {
            const int idx = tid + u * 256;
            const int r   = idx >> 3;
            const int cw  = (idx & 7) * 2;
            uint32_t* px = &sX[r * GS + cw];
            uint32_t* pw = &sW[r * GS + cw];
            float a0, a1, a2, a3;
            px[0]  = split2(xf[u].x, xf[u].y, a0, a1);
            px[1]  = split2(xf[u].z, xf[u].w, a2, a3);
            px[16] = cvt2(a0, a1);
            px[17] = cvt2(a2, a3);
            pw[0]  = split2(wf[u].x, wf[u].y, a0, a1);
            pw[1]  = split2(wf[u].z, wf[u].w, a2, a3);
            pw[16] = cvt2(a0, a1);
            pw[17] = cvt2(a2, a3);
        }
        __syncthreads();

#pragma unroll
        for (int t = 0; t < 3; t++) {
            const int ao = (t == 2) ? 16 : 0;
            const int bo = (t == 1) ? 16 : 0;
#pragma unroll
            for (int ks = 0; ks < 2; ks++) {
                const int kb = ks * 8 + p;
                uint32_t a[2][4];
#pragma unroll
                for (int mf = 0; mf < 2; mf++) {
                    const uint32_t* ax = &sX[(mw + mf * 16 + r4) * GS + ao + kb];
                    a[mf][0] = ax[0];
                    a[mf][1] = ax[8 * GS];
                    a[mf][2] = ax[4];
                    a[mf][3] = ax[8 * GS + 4];
                }
#pragma unroll
                for (int nf = 0; nf < 8; nf++) {
                    const uint32_t* bx = &sW[(nw + nf * 8 + r4) * GS + bo + kb];
                    uint32_t bfr[2];
                    bfr[0] = bx[0];
                    bfr[1] = bx[4];
                    mma_bf16(d[0][nf], a[0], bfr);
                    mma_bf16(d[1][nf], a[1], bfr);
                }
            }
        }
    }

    // epilogue: +bias, split to bf16 hi/lo, write per-head layout
#pragma unroll
    for (int mf = 0; mf < 2; mf++) {
#pragma unroll
        for (int nf = 0; nf < 8; nf++) {
            const int col  = n0 + nw + nf * 8 + 2 * p;
            const float b0 = bias[col], b1 = bias[col + 1];
            const int row0 = m0 + mw + mf * 16 + r4;
            const float v00 = d[mf][nf][0] + b0, v01 = d[mf][nf][1] + b1;
            const float v10 = d[mf][nf][2] + b0, v11 = d[mf][nf][3] + b1;
            float ra, rb;
            const uint32_t h0 = split2(v00, v01, ra, rb);
            const uint32_t l0 = cvt2(ra, rb);
            const uint32_t h1 = split2(v10, v11, ra, rb);
            const uint32_t l1 = cvt2(ra, rb);
            const size_t w0 = (size_t)row0 * 256 + (col >> 5) * 32 + ((col & 31) >> 1);
            OB[w0]            = h0;
            OB[w0 + 16]       = l0;
            OB[w0 + 8 * 256]      = h1;
            OB[w0 + 8 * 256 + 16] = l1;
        }
    }
}

// ---------------------------------------------------------------------------
// Small-M GEMM: 64x64 tile, 4x4 micro, BK=16. For M=1024 projections.
// ---------------------------------------------------------------------------
__global__ __launch_bounds__(256)
void gemm64_kernel(const float* __restrict__ X, const float* __restrict__ W,
                   const float* __restrict__ bias, float* __restrict__ C,
                   float scale)
{
    const int K = EE, N = EE;
    __shared__ float As[16][64];
    __shared__ float Bs[16][64];

    const int tid = threadIdx.x;
    const int tx  = tid & 15;
    const int ty  = tid >> 4;
    const int m0  = blockIdx.y * 64;
    const int n0  = blockIdx.x * 64;

    float acc[4][4];
#pragma unroll
    for (int i = 0; i < 4; i++)
#pragma unroll
        for (int j = 0; j < 4; j++) acc[i][j] = 0.f;

    const int lm = tid >> 2;
    const int lk = (tid & 3) * 4;
    const float* Xp = X + (size_t)(m0 + lm) * K + lk;
    const float* Wp = W + (size_t)(n0 + lm) * K + lk;

    for (int k0 = 0; k0 < K; k0 += 16) {
        const float4 xa = *(const float4*)(Xp + k0);
        const float4 wb = *(const float4*)(Wp + k0);
        __syncthreads();
        As[lk + 0][lm] = xa.x; As[lk + 1][lm] = xa.y;
        As[lk + 2][lm] = xa.z; As[lk + 3][lm] = xa.w;
        Bs[lk + 0][lm] = wb.x; Bs[lk + 1][lm] = wb.y;
        Bs[lk + 2][lm] = wb.z; Bs[lk + 3][lm] = wb.w;
        __syncthreads();
#pragma unroll
        for (int kk = 0; kk < 16; kk++) {
            float4 a = *(const float4*)&As[kk][ty * 4];
            float4 b = *(const float4*)&Bs[kk][tx * 4];
            const float av[4] = {a.x, a.y, a.z, a.w};
            const float bw[4] = {b.x, b.y, b.z, b.w};
#pragma unroll
            for (int i = 0; i < 4; i++)
#pragma unroll
                for (int j = 0; j < 4; j++)
                    acc[i][j] = fmaf(av[i], bw[j], acc[i][j]);
        }
    }

    float bv[4];
#pragma unroll
    for (int j = 0; j < 4; j++) bv[j] = bias[n0 + tx * 4 + j];

#pragma unroll
    for (int i = 0; i < 4; i++) {
        const int row = m0 + ty * 4 + i;
        float4 r;
        r.x = (acc[i][0] + bv[0]) * scale;
        r.y = (acc[i][1] + bv[1]) * scale;
        r.z = (acc[i][2] + bv[2]) * scale;
        r.w = (acc[i][3] + bv[3]) * scale;
        *(float4*)&C[(size_t)row * N + n0 + tx * 4] = r;
    }
}

// ---------------------------------------------------------------------------
// Tensor-core split-KV flash attention, double-buffered pipeline, with
// ILP-ordered MMAs: per k-step all B fragments are register-cached, then
// three passes over nf so consecutive HMMA target DIFFERENT accumulators
// (reuse distance 4 ~ 64cy > HMMA latency).
// ---------------------------------------------------------------------------
__global__ __launch_bounds__(256, 2)
void flash_mma_kernel(const float* __restrict__ qp, const float* __restrict__ mask,
                      const float* __restrict__ sf)
{
    // pool carve: sQ[2304] | sK 2x2304 | sV 2x2176 | sL 128  (words)
    __shared__ uint32_t pool[2304 + 4608 + 4352 + 128];
    uint32_t* sQ  = pool;
    uint32_t* sKb = pool + 2304;
    uint32_t* sVb = pool + 2304 + 4608;
    float*    sL  = (float*)(pool + 2304 + 4608 + 4352);
    float (*sO)[33] = (float(*)[33])(pool + 2304);   // epilogue alias over sK

    const int h     = blockIdx.x & 7;
    const int split = blockIdx.x >> 3;
    const int tq = blockIdx.y;
    const int b  = blockIdx.z;
    const int t0 = tq * 64;
    const int s_begin = split * SCHUNK;

    const int tid  = threadIdx.x;
    const int wid  = tid >> 5;
    const int lane = tid & 31;
    const int r4 = lane >> 2;
    const int p  = lane & 3;
    const int mw  = (wid & 3) * 16;      // q-row base of this warp
    const int nwi = wid >> 2;            // 0/1: s half
    const int nw  = nwi * 32;            // s base within chunk
    const float C1 = sf[h] * 1.4426950408889634f;

    const size_t bS = (size_t)b * SS;
    const float* qbase = qp + ((size_t)b * TT + t0) * EE + h * DD;
    const float* mbase = mask + ((size_t)b * TT + t0) * (size_t)SS;

    // staging index helpers
    const int kr  = tid >> 3;            // K stage row
    const int kcw = (tid & 7) * 4;       // K word col (uint4)
    const int vs2 = tid >> 3;            // s-pair row for V staging
    const int vg  = tid & 7;             // word group
    const int vsrc = h * 32 + (vg & 3) * 4 + ((vg >> 2) * 16);

    // convert Q tile (64 x 32 fp32) to hi/lo once
#pragma unroll
    for (int u = 0; u < 2; u++) {
        const int idx = tid + u * 256;
        const int r   = idx >> 3;
        const int cq  = (idx & 7) * 4;
        const float4 f = *(const float4*)(qbase + (size_t)r * EE + cq);
        const int cw = (idx & 7) * 2;
        uint32_t* px = &sQ[r * GS + cw];
        float a0, a1, a2, a3;
        px[0]  = split2(f.x, f.y, a0, a1);
        px[1]  = split2(f.z, f.w, a2, a3);
        px[16] = cvt2(a0, a1);
        px[17] = cvt2(a2, a3);
    }

    // ---- prologue: load + store chunk 0 into buffer 0
    {
        uint4 kw0 = *(const uint4*)&g_kb[(bS + s_begin + kr)      * 256 + h * 32 + kcw];
        uint4 kw1 = *(const uint4*)&g_kb[(bS + s_begin + 32 + kr) * 256 + h * 32 + kcw];
        uint4 va  = *(const uint4*)&g_vb[(bS + s_begin + 2 * vs2)     * 256 + vsrc];
        uint4 vb  = *(const uint4*)&g_vb[(bS + s_begin + 2 * vs2 + 1) * 256 + vsrc];
        *(uint4*)&sKb[kr * GS + kcw]        = kw0;
        *(uint4*)&sKb[(32 + kr) * GS + kcw] = kw1;
        uint32_t* pv = &sVb[vs2 * 68 + vg * 8];
        *(uint4*)(pv)     = make_uint4(__byte_perm(va.x, vb.x, 0x5410),
                                       __byte_perm(va.x, vb.x, 0x7632),
                                       __byte_perm(va.y, vb.y, 0x5410),
                                       __byte_perm(va.y, vb.y, 0x7632));
        *(uint4*)(pv + 4) = make_uint4(__byte_perm(va.z, vb.z, 0x5410),
                                       __byte_perm(va.z, vb.z, 0x7632),
                                       __byte_perm(va.w, vb.w, 0x5410),
                                       __byte_perm(va.w, vb.w, 0x7632));
    }
    __syncthreads();   // buffer 0 + sQ ready

    float o[4][4];
#pragma unroll
    for (int i = 0; i < 4; i++)
#pragma unroll
        for (int j = 0; j < 4; j++) o[i][j] = 0.f;
    float l2[2] = {0.f, 0.f};

#pragma unroll 2
    for (int it = 0; it < NCHUNK; it++) {
        const int s0 = s_begin + it * 64;
        const uint32_t* sK = sKb + (it & 1) * 2304;
        const uint32_t* sV = sVb + (it & 1) * 2176;

        // ---- prefetch chunk it+1 (LDG latency spans the MMA section below)
        uint4 kw0, kw1, va, vb;
        const bool more = (it + 1 < NCHUNK);
        if (more) {
            const int sn = s0 + 64;
            kw0 = *(const uint4*)&g_kb[(bS + sn + kr)      * 256 + h * 32 + kcw];
            kw1 = *(const uint4*)&g_kb[(bS + sn + 32 + kr) * 256 + h * 32 + kcw];
            va  = *(const uint4*)&g_vb[(bS + sn + 2 * vs2)     * 256 + vsrc];
            vb  = *(const uint4*)&g_vb[(bS + sn + 2 * vs2 + 1) * 256 + vsrc];
        }
        // mask for the CURRENT chunk
        float2 mk[4][2];
#pragma unroll
        for (int nf = 0; nf < 4; nf++) {
            const int col = s0 + nw + nf * 8 + 2 * p;
            const size_t rowoff = (size_t)(mw + r4) * SS;
            mk[nf][0] = *(const float2*)(mbase + rowoff + col);
            mk[nf][1] = *(const float2*)(mbase + rowoff + 8 * SS + col);
        }

        // ---- QK^T: ILP-ordered (3 passes over nf, distinct accumulators)
        float c[4][4];
#pragma unroll
        for (int nf = 0; nf < 4; nf++)
#pragma unroll
            for (int q = 0; q < 4; q++) c[nf][q] = 0.f;

#pragma unroll
        for (int ks = 0; ks < 2; ks++) {
            const int kb = ks * 8 + p;
            const uint32_t* ax = &sQ[(mw + r4) * GS + kb];
            uint32_t ah[4], al[4];
            ah[0] = ax[0];      ah[1] = ax[8 * GS];      ah[2] = ax[4];      ah[3] = ax[8 * GS + 4];
            al[0] = ax[16];     al[1] = ax[8 * GS + 16]; al[2] = ax[20];     al[3] = ax[8 * GS + 20];
            uint32_t bh[4][2], bl[4][2];
#pragma unroll
            for (int nf = 0; nf < 4; nf++) {
                const uint32_t* bx = &sK[(nw + nf * 8 + r4) * GS + kb];
                bh[nf][0] = bx[0];  bh[nf][1] = bx[4];
                bl[nf][0] = bx[16]; bl[nf][1] = bx[20];
            }
#pragma unroll
            for (int nf = 0; nf < 4; nf++) mma_bf16(c[nf], ah, bh[nf]);
#pragma unroll
            for (int nf = 0; nf < 4; nf++) mma_bf16(c[nf], ah, bl[nf]);
#pragma unroll
            for (int nf = 0; nf < 4; nf++) mma_bf16(c[nf], al, bh[nf]);
        }

        // ---- p = ex2(score_l2 + (mask-1)*C1); accumulate l
#pragma unroll
        for (int nf = 0; nf < 4; nf++) {
            c[nf][0] = ex2(fmaf(mk[nf][0].x, C1, c[nf][0]) - C1);
            c[nf][1] = ex2(fmaf(mk[nf][0].y, C1, c[nf][1]) - C1);
            c[nf][2] = ex2(fmaf(mk[nf][1].x, C1, c[nf][2]) - C1);
            c[nf][3] = ex2(fmaf(mk[nf][1].y, C1, c[nf][3]) - C1);
            l2[0] += c[nf][0] + c[nf][1];
            l2[1] += c[nf][2] + c[nf][3];
        }

        // ---- PV: ILP-ordered (3 passes over nfd, distinct accumulators)
#pragma unroll
        for (int ks = 0; ks < 2; ks++) {
            uint32_t ah[4], al[4];
            float r0, r1, r2, r3, r4f, r5, r6, r7;
            ah[0] = split2(c[2 * ks][0],     c[2 * ks][1],     r0, r1);
            ah[1] = split2(c[2 * ks][2],     c[2 * ks][3],     r2, r3);
            ah[2] = split2(c[2 * ks + 1][0], c[2 * ks + 1][1], r4f, r5);
            ah[3] = split2(c[2 * ks + 1][2], c[2 * ks + 1][3], r6, r7);
            al[0] = cvt2(r0, r1);
            al[1] = cvt2(r2, r3);
            al[2] = cvt2(r4f, r5);
            al[3] = cvt2(r6, r7);
            const int s2b = nw / 2 + ks * 8 + p;
            uint32_t vh[4][2], vl[4][2];
#pragma unroll
            for (int nfd = 0; nfd < 4; nfd++) {
                const uint32_t* bx = &sV[s2b * 68 + nfd * 8 + r4];
                vh[nfd][0] = bx[0];  vh[nfd][1] = bx[4 * 68];
                vl[nfd][0] = bx[32]; vl[nfd][1] = bx[4 * 68 + 32];
            }
#pragma unroll
            for (int nfd = 0; nfd < 4; nfd++) mma_bf16(o[nfd], ah, vh[nfd]);
#pragma unroll
            for (int nfd = 0; nfd < 4; nfd++) mma_bf16(o[nfd], ah, vl[nfd]);
#pragma unroll
            for (int nfd = 0; nfd < 4; nfd++) mma_bf16(o[nfd], al, vh[nfd]);
        }

        // ---- store chunk it+1 into the other buffer (data arrived by now)
        if (more) {
            uint32_t* sKn = sKb + ((it + 1) & 1) * 2304;
            uint32_t* sVn = sVb + ((it + 1) & 1) * 2176;
            *(uint4*)&sKn[kr * GS + kcw]        = kw0;
            *(uint4*)&sKn[(32 + kr) * GS + kcw] = kw1;
            uint32_t* pv = &sVn[vs2 * 68 + vg * 8];
            *(uint4*)(pv)     = make_uint4(__byte_perm(va.x, vb.x, 0x5410),
                                           __byte_perm(va.x, vb.x, 0x7632),
                                           __byte_perm(va.y, vb.y, 0x5410),
                                           __byte_perm(va.y, vb.y, 0x7632));
            *(uint4*)(pv + 4) = make_uint4(__byte_perm(va.z, vb.z, 0x5410),
                                           __byte_perm(va.z, vb.z, 0x7632),
                                           __byte_perm(va.w, vb.w, 0x5410),
                                           __byte_perm(va.w, vb.w, 0x7632));
        }
        __syncthreads();   // buffer it+1 ready; all reads of buffer it done
    }

    // ---- epilogue: reduce l, combine the two s-half partials of o, write
    l2[0] += __shfl_xor_sync(0xFFFFFFFFu, l2[0], 1);
    l2[0] += __shfl_xor_sync(0xFFFFFFFFu, l2[0], 2);
    l2[1] += __shfl_xor_sync(0xFFFFFFFFu, l2[1], 1);
    l2[1] += __shfl_xor_sync(0xFFFFFFFFu, l2[1], 2);
    if (p == 0) {
        sL[nwi * 64 + mw + r4]     = l2[0];
        sL[nwi * 64 + mw + 8 + r4] = l2[1];
    }
    __syncthreads();

    const int pid = (((b * NTQ + tq) * HH + h) * SPLITS + split);
    if (tid < 64)
        g_pl[pid * 64 + tid] = sL[tid] + sL[64 + tid];

    if (nwi == 1) {
#pragma unroll
        for (int nfd = 0; nfd < 4; nfd++) {
            const int col = nfd * 8 + 2 * p;
            sO[mw + r4][col]     = o[nfd][0];
            sO[mw + r4][col + 1] = o[nfd][1];
            sO[mw + 8 + r4][col]     = o[nfd][2];
            sO[mw + 8 + r4][col + 1] = o[nfd][3];
        }
    }
    __syncthreads();
    if (nwi == 0) {
        float* pob = g_po + (size_t)pid * (64 * 32);
#pragma unroll
        for (int nfd = 0; nfd < 4; nfd++) {
            const int col = nfd * 8 + 2 * p;
            float2 r0, r1;
            r0.x = o[nfd][0] + sO[mw + r4][col];
            r0.y = o[nfd][1] + sO[mw + r4][col + 1];
            r1.x = o[nfd][2] + sO[mw + 8 + r4][col];
            r1.y = o[nfd][3] + sO[mw + 8 + r4][col + 1];
            *(float2*)&pob[(mw + r4) * 32 + col]     = r0;
            *(float2*)&pob[(mw + 8 + r4) * 32 + col] = r1;
        }
    }
}

// ---------------------------------------------------------------------------
// Combine: all splits share the same implicit max -> plain sums.
// ---------------------------------------------------------------------------
__global__ __launch_bounds__(256)
void flash_combine_kernel(float* __restrict__ outp)
{
    const int g = blockIdx.x;
    const int h  = g & 7;
    const int tq = (g >> 3) & 3;
    const int b  = g >> 5;
    const int base = g * SPLITS;

    const int tid = threadIdx.x;
    const int row = tid >> 2;
    const int d0  = (tid & 3) * 8;

    float L = 0.f;
#pragma unroll
    for (int s = 0; s < SPLITS; s++)
        L += g_pl[(base + s) * 64 + row];
    const float inv = 1.f / L;

    float acc[8];
#pragma unroll
    for (int j = 0; j < 8; j++) acc[j] = 0.f;
#pragma unroll
    for (int s = 0; s < SPLITS; s++) {
        const float* p = g_po + (size_t)(base + s) * (64 * 32) + row * 32 + d0;
        const float4 a = *(const float4*)(p);
        const float4 c = *(const float4*)(p + 4);
        acc[0] += a.x; acc[1] += a.y; acc[2] += a.z; acc[3] += a.w;
        acc[4] += c.x; acc[5] += c.y; acc[6] += c.z; acc[7] += c.w;
    }

    float* ob = outp + ((size_t)b * TT + tq * 64 + row) * EE + h * DD + d0;
    float4 r0, r1;
    r0.x = acc[0] * inv; r0.y = acc[1] * inv; r0.z = acc[2] * inv; r0.w = acc[3] * inv;
    r1.x = acc[4] * inv; r1.y = acc[5] * inv; r1.z = acc[6] * inv; r1.w = acc[7] * inv;
    *(float4*)ob       = r0;
    *(float4*)(ob + 4) = r1;
}

// ---------------------------------------------------------------------------
// Launch. 5 kernel launches, no sync / alloc / memcpy / statics -> capturable.
// ---------------------------------------------------------------------------
extern "C" void kernel_launch(void* const* d_in, const int* in_sizes, int n_in,
                              void* d_out, int out_size)
{
    (void)in_sizes; (void)n_in; (void)out_size;

    const float* query = (const float*)d_in[0];
    const float* key   = (const float*)d_in[1];
    const float* value = (const float*)d_in[2];
    const float* mask  = (const float*)d_in[3];
    const float* Wq    = (const float*)d_in[4];
    const float* bq    = (const float*)d_in[5];
    const float* Wk    = (const float*)d_in[6];
    const float* bk    = (const float*)d_in[7];
    const float* Wv    = (const float*)d_in[8];
    const float* bv    = (const float*)d_in[9];
    const float* Wo    = (const float*)d_in[10];
    const float* bo    = (const float*)d_in[11];
    const float* sf    = (const float*)d_in[12];
    float* out = (float*)d_out;

    float *qp = nullptr, *att = nullptr;
    cudaGetSymbolAddress((void**)&qp,  g_qp);
    cudaGetSymbolAddress((void**)&att, g_att);

    // 1/sqrt(D) * log2(e): score arrives pre-scaled for the ex2 softmax path
    const float qscale = 0.17677669529663687f * 1.4426950408889634f;
    const dim3 blk(256);

    // K and V projections -> bf16 hi/lo per-head layout (grid.z selects K/V)
    gemm_mma_kernel<<<dim3(2, (BB * SS) / 128, 2), blk>>>(
        key, Wk, bk, value, Wv, bv);

    gemm64_kernel<<<dim3(4, (BB * TT) / 64), blk>>>(query, Wq, bq, qp, qscale);

    flash_mma_kernel<<<dim3(HH * SPLITS, NTQ, BB), blk>>>(qp, mask, sf);
    flash_combine_kernel<<<dim3(BB * NTQ * HH), blk>>>(att);

    gemm64_kernel<<<dim3(4, (BB * TT) / 64), blk>>>(att, Wo, bo, out, 1.0f);
}

// round 17
// speedup vs baseline: 1.0480x; 1.0480x over previous
#include <cuda_runtime.h>
#include <cuda_bf16.h>
#include <math.h>
#include <stdint.h>

// Problem constants (fixed by the reference)
#define BB 4
#define TT 256
#define SS 16384
#define EE 256
#define HH 8
#define DD 32

#define SPLITS 32
#define SCHUNK (SS / SPLITS)          // 512 keys per block
#define NCHUNK (SCHUNK / 64)          // 8 chunks of 64 keys
#define NQT 2                         // two 128-row q tiles
#define NPID (BB * NQT * HH * SPLITS) // 2048 partials (128 rows each)

// Scratch (allocation-free rule: __device__ globals)
__device__ float    g_qp[BB * TT * EE];        // projected Q (scaled by qscale*log2e)
__device__ uint32_t g_kb[BB * SS * 256];       // K proj bf16: row s, head h:
                                               //   words h*32+0..15 = hi pairs, +16..31 = lo
__device__ uint32_t g_vb[BB * SS * 256];       // V proj bf16, same layout
__device__ float    g_att[BB * TT * EE];
__device__ float    g_po[NPID * 128 * 32];     // unnormalized partial O
__device__ float    g_pl[NPID * 128];          // partial row sums

// ===========================================================================
// mma.sync bf16 (sm_80+ baseline; lowers to HMMA on sm_100)
// ===========================================================================
static __device__ __forceinline__ void mma_bf16(float* d, const uint32_t* a,
                                                const uint32_t* b) {
    asm volatile(
        "mma.sync.aligned.m16n8k16.row.col.f32.bf16.bf16.f32 "
        "{%0,%1,%2,%3}, {%4,%5,%6,%7}, {%8,%9}, {%0,%1,%2,%3};"
        : "+f"(d[0]), "+f"(d[1]), "+f"(d[2]), "+f"(d[3])
        : "r"(a[0]), "r"(a[1]), "r"(a[2]), "r"(a[3]), "r"(b[0]), "r"(b[1]));
}

// One-instruction pack: word = {lo half <- x, hi half <- y}
static __device__ __forceinline__ uint32_t cvt2(float x, float y) {
    uint32_t r;
    asm("cvt.rn.bf16x2.f32 %0, %1, %2;" : "=r"(r) : "f"(y), "f"(x));
    return r;
}
// Pack hi word of (x,y) and return bf16-rounding residuals
static __device__ __forceinline__ uint32_t split2(float x, float y,
                                                  float& rx, float& ry) {
    const uint32_t h = cvt2(x, y);
    rx = x - __uint_as_float(h << 16);
    ry = y - __uint_as_float(h & 0xFFFF0000u);
    return h;
}
static __device__ __forceinline__ float ex2(float x) {
    float r;
    asm("ex2.approx.f32 %0, %1;" : "=f"(r) : "f"(x));
    return r;
}

#define GS 36   // smem row stride in words: 16 hi + 16 lo + 4 pad

// ---------------------------------------------------------------------------
// bf16-split tensor-core GEMM for K/V projections (unchanged, passing).
// ---------------------------------------------------------------------------
__global__ __launch_bounds__(256, 2)
void gemm_mma_kernel(const float* __restrict__ Xk, const float* __restrict__ Wk,
                     const float* __restrict__ bk,
                     const float* __restrict__ Xv, const float* __restrict__ Wv,
                     const float* __restrict__ bv)
{
    __shared__ uint32_t sX[128 * GS];
    __shared__ uint32_t sW[128 * GS];

    const int tid  = threadIdx.x;
    const int wid  = tid >> 5;
    const int lane = tid & 31;
    const int r4 = lane >> 2;
    const int p  = lane & 3;
    const int n0 = blockIdx.x * 128;
    const int m0 = blockIdx.y * 128;
    const float* X    = blockIdx.z ? Xv : Xk;
    const float* W    = blockIdx.z ? Wv : Wk;
    const float* bias = blockIdx.z ? bv : bk;
    uint32_t*    OB   = blockIdx.z ? g_vb : g_kb;

    const int mw = (wid & 3) * 32;
    const int nw = (wid >> 2) * 64;

    float d[2][8][4];
#pragma unroll
    for (int i = 0; i < 2; i++)
#pragma unroll
        for (int j = 0; j < 8; j++)
#pragma unroll
            for (int q = 0; q < 4; q++) d[i][j][q] = 0.f;

    for (int ch = 0; ch < 8; ch++) {
        const int kc0 = ch * 32;
        float4 xf[4], wf[4];
#pragma unroll
        for (int u = 0; u < 4; u++) {
            const int idx = tid + u * 256;
            const int r   = idx >> 3;
            const int cq  = (idx & 7) * 4;
            xf[u] = *(const float4*)(X + (size_t)(m0 + r) * EE + kc0 + cq);
            wf[u] = *(const float4*)(W + (size_t)(n0 + r) * EE + kc0 + cq);
        }
        __syncthreads();
#pragma unroll
        for (int u = 0; u < 4; u++) {
            const int idx = tid + u * 256;
            const int r   = idx >> 3;
            const int cw  = (idx & 7) * 2;
            uint32_t* px = &sX[r * GS + cw];
            uint32_t* pw = &sW[r * GS + cw];
            float a0, a1, a2, a3;
            px[0]  = split2(xf[u].x, xf[u].y, a0, a1);
            px[1]  = split2(xf[u].z, xf[u].w, a2, a3);
            px[16] = cvt2(a0, a1);
            px[17] = cvt2(a2, a3);
            pw[0]  = split2(wf[u].x, wf[u].y, a0, a1);
            pw[1]  = split2(wf[u].z, wf[u].w, a2, a3);
            pw[16] = cvt2(a0, a1);
            pw[17] = cvt2(a2, a3);
        }
        __syncthreads();

#pragma unroll
        for (int t = 0; t < 3; t++) {
            const int ao = (t == 2) ? 16 : 0;
            const int bo = (t == 1) ? 16 : 0;
#pragma unroll
            for (int ks = 0; ks < 2; ks++) {
                const int kb = ks * 8 + p;
                uint32_t a[2][4];
#pragma unroll
                for (int mf = 0; mf < 2; mf++) {
                    const uint32_t* ax = &sX[(mw + mf * 16 + r4) * GS + ao + kb];
                    a[mf][0] = ax[0];
                    a[mf][1] = ax[8 * GS];
                    a[mf][2] = ax[4];
                    a[mf][3] = ax[8 * GS + 4];
                }
#pragma unroll
                for (int nf = 0; nf < 8; nf++) {
                    const uint32_t* bx = &sW[(nw + nf * 8 + r4) * GS + bo + kb];
                    uint32_t bfr[2];
                    bfr[0] = bx[0];
                    bfr[1] = bx[4];
                    mma_bf16(d[0][nf], a[0], bfr);
                    mma_bf16(d[1][nf], a[1], bfr);
                }
            }
        }
    }

    // epilogue: +bias, split to bf16 hi/lo, write per-head layout
#pragma unroll
    for (int mf = 0; mf < 2; mf++) {
#pragma unroll
        for (int nf = 0; nf < 8; nf++) {
            const int col  = n0 + nw + nf * 8 + 2 * p;
            const float b0 = bias[col], b1 = bias[col + 1];
            const int row0 = m0 + mw + mf * 16 + r4;
            const float v00 = d[mf][nf][0] + b0, v01 = d[mf][nf][1] + b1;
            const float v10 = d[mf][nf][2] + b0, v11 = d[mf][nf][3] + b1;
            float ra, rb;
            const uint32_t h0 = split2(v00, v01, ra, rb);
            const uint32_t l0 = cvt2(ra, rb);
            const uint32_t h1 = split2(v10, v11, ra, rb);
            const uint32_t l1 = cvt2(ra, rb);
            const size_t w0 = (size_t)row0 * 256 + (col >> 5) * 32 + ((col & 31) >> 1);
            OB[w0]            = h0;
            OB[w0 + 16]       = l0;
            OB[w0 + 8 * 256]      = h1;
            OB[w0 + 8 * 256 + 16] = l1;
        }
    }
}

// ---------------------------------------------------------------------------
// Small-M GEMM: 64x64 tile, 4x4 micro, BK=16. For M=1024 projections.
// ---------------------------------------------------------------------------
__global__ __launch_bounds__(256)
void gemm64_kernel(const float* __restrict__ X, const float* __restrict__ W,
                   const float* __restrict__ bias, float* __restrict__ C,
                   float scale)
{
    const int K = EE, N = EE;
    __shared__ float As[16][64];
    __shared__ float Bs[16][64];

    const int tid = threadIdx.x;
    const int tx  = tid & 15;
    const int ty  = tid >> 4;
    const int m0  = blockIdx.y * 64;
    const int n0  = blockIdx.x * 64;

    float acc[4][4];
#pragma unroll
    for (int i = 0; i < 4; i++)
#pragma unroll
        for (int j = 0; j < 4; j++) acc[i][j] = 0.f;

    const int lm = tid >> 2;
    const int lk = (tid & 3) * 4;
    const float* Xp = X + (size_t)(m0 + lm) * K + lk;
    const float* Wp = W + (size_t)(n0 + lm) * K + lk;

    for (int k0 = 0; k0 < K; k0 += 16) {
        const float4 xa = *(const float4*)(Xp + k0);
        const float4 wb = *(const float4*)(Wp + k0);
        __syncthreads();
        As[lk + 0][lm] = xa.x; As[lk + 1][lm] = xa.y;
        As[lk + 2][lm] = xa.z; As[lk + 3][lm] = xa.w;
        Bs[lk + 0][lm] = wb.x; Bs[lk + 1][lm] = wb.y;
        Bs[lk + 2][lm] = wb.z; Bs[lk + 3][lm] = wb.w;
        __syncthreads();
#pragma unroll
        for (int kk = 0; kk < 16; kk++) {
            float4 a = *(const float4*)&As[kk][ty * 4];
            float4 b = *(const float4*)&Bs[kk][tx * 4];
            const float av[4] = {a.x, a.y, a.z, a.w};
            const float bw[4] = {b.x, b.y, b.z, b.w};
#pragma unroll
            for (int i = 0; i < 4; i++)
#pragma unroll
                for (int j = 0; j < 4; j++)
                    acc[i][j] = fmaf(av[i], bw[j], acc[i][j]);
        }
    }

    float bv[4];
#pragma unroll
    for (int j = 0; j < 4; j++) bv[j] = bias[n0 + tx * 4 + j];

#pragma unroll
    for (int i = 0; i < 4; i++) {
        const int row = m0 + ty * 4 + i;
        float4 r;
        r.x = (acc[i][0] + bv[0]) * scale;
        r.y = (acc[i][1] + bv[1]) * scale;
        r.z = (acc[i][2] + bv[2]) * scale;
        r.w = (acc[i][3] + bv[3]) * scale;
        *(float4*)&C[(size_t)row * N + n0 + tx * 4] = r;
    }
}

// ---------------------------------------------------------------------------
// Tensor-core split-KV flash attention, 2-qtile-fused.
// Block = (b, h, tq-half, split): 128 q rows x 512 keys. 8 warps, each
// m16 x FULL 64-key width (no s-split -> no cross-warp O combine).
// Q fragments are loop-invariant -> loaded ONCE into registers.
// Score tile processed in two 32-col halves to bound register pressure.
// Double-buffered K/V smem; one barrier per chunk.
// ---------------------------------------------------------------------------
__global__ __launch_bounds__(256, 2)
void flash_mma_kernel(const float* __restrict__ qp, const float* __restrict__ mask,
                      const float* __restrict__ sf)
{
    __shared__ uint32_t sK[2][64 * GS];    // s rows: 16 hi | 16 lo | 4 pad
    __shared__ uint32_t sV[2][32 * 68];    // s2 rows: 32 paired-hi | 32 paired-lo | 4 pad

    const int h     = blockIdx.x & 7;
    const int tqh   = blockIdx.x >> 3;     // 0/1: which 128-row q half
    const int split = blockIdx.y;
    const int b     = blockIdx.z;
    const int t0    = tqh * 128;
    const int s_begin = split * SCHUNK;

    const int tid  = threadIdx.x;
    const int wid  = tid >> 5;             // 0..7
    const int lane = tid & 31;
    const int r4 = lane >> 2;
    const int p  = lane & 3;
    const int mw = wid * 16;               // q-row base of this warp (0..112)
    const float C1 = sf[h] * 1.4426950408889634f;

    const size_t bS = (size_t)b * SS;
    const float* qbase = qp + ((size_t)b * TT + t0) * EE + h * DD;
    const float* mbase = mask + ((size_t)b * TT + t0) * (size_t)SS;

    // ---- Q fragments, loop-invariant, straight to registers
    uint32_t qh[2][4], ql[2][4];
#pragma unroll
    for (int ks = 0; ks < 2; ks++) {
        const int c0 = 16 * ks + 2 * p;
        const float2 f00 = *(const float2*)(qbase + (size_t)(mw + r4) * EE + c0);
        const float2 f10 = *(const float2*)(qbase + (size_t)(mw + 8 + r4) * EE + c0);
        const float2 f01 = *(const float2*)(qbase + (size_t)(mw + r4) * EE + c0 + 8);
        const float2 f11 = *(const float2*)(qbase + (size_t)(mw + 8 + r4) * EE + c0 + 8);
        float ra, rb;
        qh[ks][0] = split2(f00.x, f00.y, ra, rb); ql[ks][0] = cvt2(ra, rb);
        qh[ks][1] = split2(f10.x, f10.y, ra, rb); ql[ks][1] = cvt2(ra, rb);
        qh[ks][2] = split2(f01.x, f01.y, ra, rb); ql[ks][2] = cvt2(ra, rb);
        qh[ks][3] = split2(f11.x, f11.y, ra, rb); ql[ks][3] = cvt2(ra, rb);
    }

    // staging index helpers (256 threads)
    const int kr   = tid >> 2;             // 0..63 K row
    const int kcw  = (tid & 3) * 8;        // K word col base (2x uint4)
    const int vs2  = tid >> 3;             // 0..31 s-pair row
    const int vg   = tid & 7;              // word group
    const int vsrc = h * 32 + (vg & 3) * 4 + ((vg >> 2) * 16);

    // ---- prologue: stage chunk 0 into buffer 0
    {
        const uint4 kw0 = *(const uint4*)&g_kb[(bS + s_begin + kr) * 256 + h * 32 + kcw];
        const uint4 kw1 = *(const uint4*)&g_kb[(bS + s_begin + kr) * 256 + h * 32 + kcw + 4];
        const uint4 va  = *(const uint4*)&g_vb[(bS + s_begin + 2 * vs2)     * 256 + vsrc];
        const uint4 vb  = *(const uint4*)&g_vb[(bS + s_begin + 2 * vs2 + 1) * 256 + vsrc];
        *(uint4*)&sK[0][kr * GS + kcw]     = kw0;
        *(uint4*)&sK[0][kr * GS + kcw + 4] = kw1;
        uint32_t* pv = &sV[0][vs2 * 68 + vg * 8];
        *(uint4*)(pv)     = make_uint4(__byte_perm(va.x, vb.x, 0x5410),
                                       __byte_perm(va.x, vb.x, 0x7632),
                                       __byte_perm(va.y, vb.y, 0x5410),
                                       __byte_perm(va.y, vb.y, 0x7632));
        *(uint4*)(pv + 4) = make_uint4(__byte_perm(va.z, vb.z, 0x5410),
                                       __byte_perm(va.z, vb.z, 0x7632),
                                       __byte_perm(va.w, vb.w, 0x5410),
                                       __byte_perm(va.w, vb.w, 0x7632));
    }
    __syncthreads();

    float o[4][4];
#pragma unroll
    for (int i = 0; i < 4; i++)
#pragma unroll
        for (int j = 0; j < 4; j++) o[i][j] = 0.f;
    float l2[2] = {0.f, 0.f};

    for (int it = 0; it < NCHUNK; it++) {
        const int s0  = s_begin + it * 64;
        const int cur = it & 1;

        // ---- prefetch next chunk (LDG latency spans the MMA work below)
        uint4 kw0, kw1, va, vb;
        const bool more = (it + 1 < NCHUNK);
        if (more) {
            const int sn = s0 + 64;
            kw0 = *(const uint4*)&g_kb[(bS + sn + kr) * 256 + h * 32 + kcw];
            kw1 = *(const uint4*)&g_kb[(bS + sn + kr) * 256 + h * 32 + kcw + 4];
            va  = *(const uint4*)&g_vb[(bS + sn + 2 * vs2)     * 256 + vsrc];
            vb  = *(const uint4*)&g_vb[(bS + sn + 2 * vs2 + 1) * 256 + vsrc];
        }

        // ---- two 32-key halves of the 64-key chunk
#pragma unroll
        for (int hf = 0; hf < 2; hf++) {
            // mask for this half (issued before QK; consumed after)
            float2 mk[4][2];
#pragma unroll
            for (int j = 0; j < 4; j++) {
                const int col = s0 + (4 * hf + j) * 8 + 2 * p;
                mk[j][0] = *(const float2*)(mbase + (size_t)(mw + r4) * SS + col);
                mk[j][1] = *(const float2*)(mbase + (size_t)(mw + 8 + r4) * SS + col);
            }

            // QK^T for cols (4hf..4hf+3)*8
            float c[4][4];
#pragma unroll
            for (int j = 0; j < 4; j++)
#pragma unroll
                for (int q = 0; q < 4; q++) c[j][q] = 0.f;

#pragma unroll
            for (int ks = 0; ks < 2; ks++) {
                const int kb = ks * 8 + p;
                uint32_t bh[4][2], bl[4][2];
#pragma unroll
                for (int j = 0; j < 4; j++) {
                    const uint32_t* bx = &sK[cur][((4 * hf + j) * 8 + r4) * GS + kb];
                    bh[j][0] = bx[0];  bh[j][1] = bx[4];
                    bl[j][0] = bx[16]; bl[j][1] = bx[20];
                }
#pragma unroll
                for (int j = 0; j < 4; j++) mma_bf16(c[j], qh[ks], bh[j]);
#pragma unroll
                for (int j = 0; j < 4; j++) mma_bf16(c[j], qh[ks], bl[j]);
#pragma unroll
                for (int j = 0; j < 4; j++) mma_bf16(c[j], ql[ks], bh[j]);
            }

            // softmax numerator (static max C1) + row-sum accumulation
#pragma unroll
            for (int j = 0; j < 4; j++) {
                c[j][0] = ex2(fmaf(mk[j][0].x, C1, c[j][0]) - C1);
                c[j][1] = ex2(fmaf(mk[j][0].y, C1, c[j][1]) - C1);
                c[j][2] = ex2(fmaf(mk[j][1].x, C1, c[j][2]) - C1);
                c[j][3] = ex2(fmaf(mk[j][1].y, C1, c[j][3]) - C1);
                l2[0] += c[j][0] + c[j][1];
                l2[1] += c[j][2] + c[j][3];
            }

            // PV for this half's 32 keys
#pragma unroll
            for (int ksp = 0; ksp < 2; ksp++) {
                uint32_t ah[4], al[4];
                float r0, r1, r2, r3, r4f, r5, r6, r7;
                ah[0] = split2(c[2 * ksp][0],     c[2 * ksp][1],     r0, r1);
                ah[1] = split2(c[2 * ksp][2],     c[2 * ksp][3],     r2, r3);
                ah[2] = split2(c[2 * ksp + 1][0], c[2 * ksp + 1][1], r4f, r5);
                ah[3] = split2(c[2 * ksp + 1][2], c[2 * ksp + 1][3], r6, r7);
                al[0] = cvt2(r0, r1);
                al[1] = cvt2(r2, r3);
                al[2] = cvt2(r4f, r5);
                al[3] = cvt2(r6, r7);
                const int s2b = (2 * hf + ksp) * 8 + p;
                uint32_t vh[4][2], vl[4][2];
#pragma unroll
                for (int nfd = 0; nfd < 4; nfd++) {
                    const uint32_t* bx = &sV[cur][s2b * 68 + nfd * 8 + r4];
                    vh[nfd][0] = bx[0];  vh[nfd][1] = bx[4 * 68];
                    vl[nfd][0] = bx[32]; vl[nfd][1] = bx[4 * 68 + 32];
                }
#pragma unroll
                for (int nfd = 0; nfd < 4; nfd++) mma_bf16(o[nfd], ah, vh[nfd]);
#pragma unroll
                for (int nfd = 0; nfd < 4; nfd++) mma_bf16(o[nfd], ah, vl[nfd]);
#pragma unroll
                for (int nfd = 0; nfd < 4; nfd++) mma_bf16(o[nfd], al, vh[nfd]);
            }
        }

        // ---- store next chunk into the other buffer
        if (more) {
            const int nxt = cur ^ 1;
            *(uint4*)&sK[nxt][kr * GS + kcw]     = kw0;
            *(uint4*)&sK[nxt][kr * GS + kcw + 4] = kw1;
            uint32_t* pv = &sV[nxt][vs2 * 68 + vg * 8];
            *(uint4*)(pv)     = make_uint4(__byte_perm(va.x, vb.x, 0x5410),
                                           __byte_perm(va.x, vb.x, 0x7632),
                                           __byte_perm(va.y, vb.y, 0x5410),
                                           __byte_perm(va.y, vb.y, 0x7632));
            *(uint4*)(pv + 4) = make_uint4(__byte_perm(va.z, vb.z, 0x5410),
                                           __byte_perm(va.z, vb.z, 0x7632),
                                           __byte_perm(va.w, vb.w, 0x5410),
                                           __byte_perm(va.w, vb.w, 0x7632));
        }
        __syncthreads();
    }

    // ---- epilogue (per-warp independent: full d width per warp)
    const int pid = (((b * NQT + tqh) * HH + h) * SPLITS + split);

    l2[0] += __shfl_xor_sync(0xFFFFFFFFu, l2[0], 1);
    l2[0] += __shfl_xor_sync(0xFFFFFFFFu, l2[0], 2);
    l2[1] += __shfl_xor_sync(0xFFFFFFFFu, l2[1], 1);
    l2[1] += __shfl_xor_sync(0xFFFFFFFFu, l2[1], 2);
    if (p == 0) {
        g_pl[pid * 128 + mw + r4]     = l2[0];
        g_pl[pid * 128 + mw + 8 + r4] = l2[1];
    }

    float* pob = g_po + (size_t)pid * (128 * 32);
#pragma unroll
    for (int nfd = 0; nfd < 4; nfd++) {
        const int col = nfd * 8 + 2 * p;
        float2 r0, r1;
        r0.x = o[nfd][0]; r0.y = o[nfd][1];
        r1.x = o[nfd][2]; r1.y = o[nfd][3];
        *(float2*)&pob[(mw + r4) * 32 + col]     = r0;
        *(float2*)&pob[(mw + 8 + r4) * 32 + col] = r1;
    }
}

// ---------------------------------------------------------------------------
// Combine: all splits share the same implicit max -> plain sums.
// grid = (BB*NQT*HH, 2): block g handles 128 rows x 16 d-cols.
// ---------------------------------------------------------------------------
__global__ __launch_bounds__(256)
void flash_combine_kernel(float* __restrict__ outp)
{
    __shared__ float sLc[128];

    const int g   = blockIdx.x;               // ((b*NQT + tqh)*HH + h)
    const int h   = g & 7;
    const int tqh = (g >> 3) & 1;
    const int b   = g >> 4;
    const int base = g * SPLITS;

    const int tid = threadIdx.x;
    const int row = tid >> 1;                 // 0..127
    const int d0  = (tid & 1) * 8 + blockIdx.y * 16;

    if (tid < 128) {
        float L = 0.f;
#pragma unroll
        for (int s = 0; s < SPLITS; s++)
            L += g_pl[(base + s) * 128 + tid];
        sLc[tid] = 1.f / L;
    }
    __syncthreads();

    float acc[8];
#pragma unroll
    for (int j = 0; j < 8; j++) acc[j] = 0.f;
#pragma unroll
    for (int s = 0; s < SPLITS; s++) {
        const float* p = g_po + (size_t)(base + s) * (128 * 32) + row * 32 + d0;
        const float4 a = *(const float4*)(p);
        const float4 c = *(const float4*)(p + 4);
        acc[0] += a.x; acc[1] += a.y; acc[2] += a.z; acc[3] += a.w;
        acc[4] += c.x; acc[5] += c.y; acc[6] += c.z; acc[7] += c.w;
    }

    const float inv = sLc[row];
    float* ob = outp + ((size_t)b * TT + tqh * 128 + row) * EE + h * DD + d0;
    float4 r0, r1;
    r0.x = acc[0] * inv; r0.y = acc[1] * inv; r0.z = acc[2] * inv; r0.w = acc[3] * inv;
    r1.x = acc[4] * inv; r1.y = acc[5] * inv; r1.z = acc[6] * inv; r1.w = acc[7] * inv;
    *(float4*)ob       = r0;
    *(float4*)(ob + 4) = r1;
}

// ---------------------------------------------------------------------------
// Launch. 5 kernel launches, no sync / alloc / memcpy / statics -> capturable.
// ---------------------------------------------------------------------------
extern "C" void kernel_launch(void* const* d_in, const int* in_sizes, int n_in,
                              void* d_out, int out_size)
{
    (void)in_sizes; (void)n_in; (void)out_size;

    const float* query = (const float*)d_in[0];
    const float* key   = (const float*)d_in[1];
    const float* value = (const float*)d_in[2];
    const float* mask  = (const float*)d_in[3];
    const float* Wq    = (const float*)d_in[4];
    const float* bq    = (const float*)d_in[5];
    const float* Wk    = (const float*)d_in[6];
    const float* bk    = (const float*)d_in[7];
    const float* Wv    = (const float*)d_in[8];
    const float* bv    = (const float*)d_in[9];
    const float* Wo    = (const float*)d_in[10];
    const float* bo    = (const float*)d_in[11];
    const float* sf    = (const float*)d_in[12];
    float* out = (float*)d_out;

    float *qp = nullptr, *att = nullptr;
    cudaGetSymbolAddress((void**)&qp,  g_qp);
    cudaGetSymbolAddress((void**)&att, g_att);

    // 1/sqrt(D) * log2(e): score arrives pre-scaled for the ex2 softmax path
    const float qscale = 0.17677669529663687f * 1.4426950408889634f;
    const dim3 blk(256);

    // K and V projections -> bf16 hi/lo per-head layout (grid.z selects K/V)
    gemm_mma_kernel<<<dim3(2, (BB * SS) / 128, 2), blk>>>(
        key, Wk, bk, value, Wv, bv);

    gemm64_kernel<<<dim3(4, (BB * TT) / 64), blk>>>(query, Wq, bq, qp, qscale);

    flash_mma_kernel<<<dim3(HH * NQT, SPLITS, BB), blk>>>(qp, mask, sf);
    flash_combine_kernel<<<dim3(BB * NQT * HH, 2), blk>>>(att);

    gemm64_kernel<<<dim3(4, (BB * TT) / 64), blk>>>(att, Wo, bo, out, 1.0f);
}